// round 15
// baseline (speedup 1.0000x reference)
#include <cuda_runtime.h>
#include <cuda_bf16.h>
#include <math.h>
#include <stdint.h>

#define TT 1024
#define CC 2048
#define HH 32
#define TC (TT*CC)
#define EPSGN 0.00064f

// ---------------- scratch ----------------
__device__ __align__(128) float g_scratch[16ull*TC + 2ull*TT*128 + (size_t)TT*64 + 4ull*TT*16];
__device__ __align__(128) __nv_bfloat16 g_bf[8ull*CC*CC + 8ull*TT*CC];

#define O_DXP   ((size_t)0*TC)
#define O_XXX   ((size_t)1*TC)
#define O_XRG   ((size_t)2*TC)
#define O_XWA   ((size_t)3*TC)
#define O_XK    ((size_t)4*TC)
#define O_XV    ((size_t)5*TC)
#define O_R     ((size_t)6*TC)
#define O_KRAW  ((size_t)7*TC)
#define O_V     ((size_t)8*TC)
#define O_DEC   ((size_t)9*TC)
#define O_A     ((size_t)10*TC)
#define O_KK    ((size_t)11*TC)
#define O_K     ((size_t)12*TC)
#define O_G     ((size_t)13*TC)
#define O_Y     ((size_t)14*TC)
#define O_HMIX  ((size_t)16*TC)
#define O_GH    (O_HMIX + (size_t)TT*128)
#define O_HD    (O_GH   + (size_t)TT*128)
#define O_HAAA  (O_HD   + (size_t)TT*64)
#define O_HMA   (O_HAAA + (size_t)TT*16)
#define O_HMK   (O_HMA  + (size_t)TT*16)
#define O_HKKK  (O_HMK  + (size_t)TT*16)

// ---------------- helpers ----------------
__device__ __forceinline__ uint32_t smem_u32(const void* p) {
    uint32_t a;
    asm("{ .reg .u64 t; cvta.to.shared.u64 t, %1; cvt.u32.u64 %0, t; }" : "=r"(a) : "l"(p));
    return a;
}
__device__ __forceinline__ void ldm4(uint32_t r[4], uint32_t a) {
    asm volatile("ldmatrix.sync.aligned.m8n8.x4.shared.b16 {%0,%1,%2,%3}, [%4];"
                 : "=r"(r[0]), "=r"(r[1]), "=r"(r[2]), "=r"(r[3]) : "r"(a));
}
__device__ __forceinline__ void mma16816(float c[4], const uint32_t a[4], uint32_t b0, uint32_t b1) {
    asm volatile("mma.sync.aligned.m16n8k16.row.col.f32.bf16.bf16.f32 "
                 "{%0,%1,%2,%3},{%4,%5,%6,%7},{%8,%9},{%0,%1,%2,%3};"
                 : "+f"(c[0]), "+f"(c[1]), "+f"(c[2]), "+f"(c[3])
                 : "r"(a[0]), "r"(a[1]), "r"(a[2]), "r"(a[3]), "r"(b0), "r"(b1));
}
#define CPA16(dst, src) asm volatile("cp.async.ca.shared.global [%0], [%1], 16;" :: "r"(dst), "l"(src))
#define CPA4(dst, src)  asm volatile("cp.async.ca.shared.global [%0], [%1], 4;"  :: "r"(dst), "l"(src))
#define CPA_COMMIT() asm volatile("cp.async.commit_group;" ::: "memory")

// ---------------- k_init: tokshift + wprep x4 ----------------
__global__ void k_init(const float* __restrict__ x, const float* __restrict__ maa_x,
                       float* __restrict__ dxp, float* __restrict__ xxx,
                       const float* __restrict__ Wq, const float* __restrict__ Wk,
                       const float* __restrict__ Wv, const float* __restrict__ Wo,
                       __nv_bfloat16* __restrict__ BF) {
    const int bid = blockIdx.x, tid = threadIdx.x;
    if (bid < 8192) {
        int idx = bid * 256 + tid;
        int t = idx >> 11, c = idx & (CC - 1);
        float xv = x[idx];
        float pv = (t > 0) ? x[idx - CC] : 0.0f;
        float dx = pv - xv;
        dxp[idx] = dx;
        xxx[idx] = fmaf(dx, maa_x[c], xv);
        return;
    }
    __shared__ float tl[32][33];
    const int wb = bid - 8192;
    const int widx = wb >> 12;
    const int tile = wb & 4095;
    const float* W = (widx == 0) ? Wq : (widx == 1) ? Wk : (widx == 2) ? Wv : Wo;
    __nv_bfloat16* Thi = BF + (size_t)widx * 2 * CC * CC;
    __nv_bfloat16* Tlo = Thi + (size_t)CC * CC;
    const int n0 = (tile & 63) * 32, k0 = (tile >> 6) * 32;
    const int tx = tid & 31, ty = tid >> 5;
#pragma unroll
    for (int j = 0; j < 4; j++)
        tl[ty + j * 8][tx] = W[(size_t)(k0 + ty + j * 8) * CC + n0 + tx];
    __syncthreads();
#pragma unroll
    for (int j = 0; j < 4; j++) {
        float v = tl[tx][ty + j * 8];
        __nv_bfloat16 h = __float2bfloat16(v);
        size_t o = (size_t)(n0 + ty + j * 8) * CC + k0 + tx;
        Thi[o] = h;
        Tlo[o] = __float2bfloat16(v - __bfloat162float(h));
    }
}

// ---------------- k_proj ----------------
template <int NN, int SPLIT, int ACT0, int ACT1>
__global__ __launch_bounds__(256) void k_proj(const float* __restrict__ A,
                                              const float* __restrict__ W0,
                                              const float* __restrict__ W1,
                                              float* __restrict__ out0,
                                              float* __restrict__ out1) {
    constexpr int G = 256 / NN;
    constexpr int R = 8 / G;
    constexpr int WCH = 64 * NN;
    extern __shared__ __align__(16) float psm[];
    float* Ws = psm;
    float* As = psm + 2 * WCH;
    const uint32_t ws_b = smem_u32(Ws);
    const uint32_t as_b = smem_u32(As);

    const int tid = threadIdx.x;
    const int n = tid % NN, g = tid / NN;
    const int r0 = blockIdx.x * 8;

    auto load_stage = [&](int kc, int stg) {
#pragma unroll
        for (int j = 0; j < WCH / 1024; j++) {
            int i = (tid + j * 256) * 4;
            int row = i / NN, col = i % NN;
            const float* src = (col < SPLIT)
                ? (W0 + (size_t)(kc + row) * SPLIT + col)
                : (W1 + (size_t)(kc + row) * (NN - SPLIT) + (col - SPLIT));
            CPA16(ws_b + (uint32_t)(stg * WCH + i) * 4, src);
        }
#pragma unroll
        for (int j = 0; j < 2; j++) {
            int i = tid + j * 256;
            int row = i >> 6, k = i & 63;
            CPA4(as_b + (uint32_t)(stg * 512 + k * 8 + row) * 4,
                 A + (size_t)(r0 + row) * CC + kc + k);
        }
        CPA_COMMIT();
    };

    float acc[R];
#pragma unroll
    for (int i = 0; i < R; i++) acc[i] = 0.f;

    load_stage(0, 0);
    for (int ch = 0; ch < 32; ch++) {
        const int b = ch & 1;
        if (ch + 1 < 32) {
            load_stage((ch + 1) * 64, b ^ 1);
            asm volatile("cp.async.wait_group 1;" ::: "memory");
        } else {
            asm volatile("cp.async.wait_group 0;" ::: "memory");
        }
        __syncthreads();
        const float* ws = Ws + b * WCH;
        const float* as = As + b * 512;
#pragma unroll 8
        for (int k = 0; k < 64; k++) {
            float wv = ws[k * NN + n];
            if (R == 4) {
                float4 a4 = *(const float4*)&as[k * 8 + g * 4];
                acc[0] = fmaf(a4.x, wv, acc[0]);
                acc[1] = fmaf(a4.y, wv, acc[1]);
                acc[2] = fmaf(a4.z, wv, acc[2]);
                acc[3] = fmaf(a4.w, wv, acc[3]);
            } else if (R == 2) {
                float2 a2 = *(const float2*)&as[k * 8 + g * 2];
                acc[0] = fmaf(a2.x, wv, acc[0]);
                acc[1] = fmaf(a2.y, wv, acc[1]);
            } else {
                acc[0] = fmaf(as[k * 8 + g], wv, acc[0]);
            }
        }
        __syncthreads();
    }

#pragma unroll
    for (int i = 0; i < R; i++) {
        int row = r0 + g * R + i;
        float v = acc[i];
        if (n < SPLIT) {
            if (ACT0) v = tanhf(v);
            out0[(size_t)row * SPLIT + n] = v;
        } else {
            if (ACT1) v = tanhf(v);
            out1[(size_t)row * (NN - SPLIT) + (n - SPLIT)] = v;
        }
    }
}

// ---------------- mix apply (+ bf16 hi/lo emission) ----------------
__global__ void k_mix_apply(const float* __restrict__ x, const float* __restrict__ dxp,
                            const float* __restrict__ hmix, const float* __restrict__ w2full,
                            const float* __restrict__ tm0, const float* __restrict__ tm1,
                            const float* __restrict__ tm2, const float* __restrict__ tm3,
                            float* __restrict__ o0, float* __restrict__ o1,
                            float* __restrict__ o2, float* __restrict__ o3,
                            __nv_bfloat16* __restrict__ bh0, __nv_bfloat16* __restrict__ bl0,
                            __nv_bfloat16* __restrict__ bh2, __nv_bfloat16* __restrict__ bl2,
                            __nv_bfloat16* __restrict__ bh3, __nv_bfloat16* __restrict__ bl3) {
    const int f = blockIdx.z, t0 = blockIdx.y * 8;
    const int c = blockIdx.x * 128 + threadIdx.x;
    __shared__ float hm[8][32];
    for (int i = threadIdx.x; i < 8 * 32; i += 128) {
        int tt = i >> 5, d = i & 31;
        hm[tt][d] = hmix[(size_t)(t0 + tt) * 128 + f * 32 + d];
    }
    __syncthreads();
    const float* w2 = w2full + (size_t)f * 32 * CC;
    float acc[8];
#pragma unroll
    for (int i = 0; i < 8; i++) acc[i] = 0.f;
#pragma unroll 8
    for (int d = 0; d < 32; d++) {
        float wv = w2[(size_t)d * CC + c];
#pragma unroll
        for (int tt = 0; tt < 8; tt++) acc[tt] = fmaf(hm[tt][d], wv, acc[tt]);
    }
    const float* tm  = (f == 0) ? tm0 : (f == 1) ? tm1 : (f == 2) ? tm2 : tm3;
    float*       out = (f == 0) ? o0  : (f == 1) ? o1  : (f == 2) ? o2  : o3;
    __nv_bfloat16* ph = (f == 0) ? bh0 : (f == 2) ? bh2 : (f == 3) ? bh3 : nullptr;
    __nv_bfloat16* pl = (f == 0) ? bl0 : (f == 2) ? bl2 : (f == 3) ? bl3 : nullptr;
    float tmv = tm[c];
#pragma unroll
    for (int tt = 0; tt < 8; tt++) {
        size_t idx = (size_t)(t0 + tt) * CC + c;
        float v = fmaf(dxp[idx], tmv + acc[tt], x[idx]);
        out[idx] = v;
        if (f != 1) {
            __nv_bfloat16 h = __float2bfloat16(v);
            ph[idx] = h;
            pl[idx] = __float2bfloat16(v - __bfloat162float(h));
        }
    }
}

// ---------------- mma.sync split-bf16 GEMM: CTA tile 128x64, 2 CTAs/SM --------
// stage: Ahi/Alo 128 rows + Bhi/Blo 64 rows, RS=72 halves row stride.
#define RS 72
#define T_A (128 * RS)
#define T_B (64 * RS)
#define STAGE_H (2 * T_A + 2 * T_B)
#define GM_SMEM (2 * STAGE_H * 2)
__global__ __launch_bounds__(256, 2) void k_bigmm(
    const __nv_bfloat16* __restrict__ Ahi, const __nv_bfloat16* __restrict__ Alo,
    const __nv_bfloat16* __restrict__ Bhi, const __nv_bfloat16* __restrict__ Blo,
    float* __restrict__ C) {
    extern __shared__ __align__(16) __nv_bfloat16 sm[];
    const int tid = threadIdx.x, wid = tid >> 5, lane = tid & 31;
    const int bn = blockIdx.x * 64, bm = blockIdx.y * 128;
    const int wm = wid & 3, wn = wid >> 2;     // warp tile 32x32
    const uint32_t sb = smem_u32(sm);

    const __nv_bfloat16* gsrc[4] = {
        Ahi + (size_t)bm * CC, Alo + (size_t)bm * CC,
        Bhi + (size_t)bn * CC, Blo + (size_t)bn * CC };

    float acc[2][4][4];
#pragma unroll
    for (int a = 0; a < 2; a++)
#pragma unroll
        for (int b = 0; b < 4; b++)
#pragma unroll
            for (int c = 0; c < 4; c++) acc[a][b][c] = 0.f;

    const int lr = tid >> 3, ls = tid & 7;   // 32 rows x 8 16B-segs per pass
    auto load_stage = [&](int kc, int stg) {
#pragma unroll
        for (int tl = 0; tl < 2; tl++) {     // A hi/lo: 128 rows
            const __nv_bfloat16* s = gsrc[tl] + kc;
            uint32_t d = sb + (uint32_t)(stg * STAGE_H + tl * T_A) * 2;
#pragma unroll
            for (int j = 0; j < 4; j++) {
                int rr = lr + j * 32;
                CPA16(d + (uint32_t)(rr * RS + ls * 8) * 2, s + (size_t)rr * CC + ls * 8);
            }
        }
#pragma unroll
        for (int tl = 2; tl < 4; tl++) {     // B hi/lo: 64 rows
            const __nv_bfloat16* s = gsrc[tl] + kc;
            uint32_t d = sb + (uint32_t)(stg * STAGE_H + 2 * T_A + (tl - 2) * T_B) * 2;
#pragma unroll
            for (int j = 0; j < 2; j++) {
                int rr = lr + j * 32;
                CPA16(d + (uint32_t)(rr * RS + ls * 8) * 2, s + (size_t)rr * CC + ls * 8);
            }
        }
        CPA_COMMIT();
    };

    const int KT = CC / 64;
    load_stage(0, 0);

    for (int kt = 0; kt < KT; kt++) {
        const int stg = kt & 1;
        if (kt + 1 < KT) {
            load_stage((kt + 1) * 64, stg ^ 1);
            asm volatile("cp.async.wait_group 1;" ::: "memory");
        } else {
            asm volatile("cp.async.wait_group 0;" ::: "memory");
        }
        __syncthreads();

        const uint32_t sA_hi = sb + (uint32_t)(stg * STAGE_H) * 2;
        const uint32_t sA_lo = sb + (uint32_t)(stg * STAGE_H + T_A) * 2;
        const uint32_t sB_hi = sb + (uint32_t)(stg * STAGE_H + 2 * T_A) * 2;
        const uint32_t sB_lo = sb + (uint32_t)(stg * STAGE_H + 2 * T_A + T_B) * 2;

#pragma unroll
        for (int ks = 0; ks < 4; ks++) {
            uint32_t ah[2][4], al[2][4], bh[2][4], bl[2][4];
#pragma unroll
            for (int mf = 0; mf < 2; mf++) {
                int row = wm * 32 + mf * 16 + (lane & 15);
                int col = ks * 16 + ((lane >> 4) << 3);
                uint32_t off = (uint32_t)(row * RS + col) * 2;
                ldm4(ah[mf], sA_hi + off);
                ldm4(al[mf], sA_lo + off);
            }
#pragma unroll
            for (int p = 0; p < 2; p++) {
                int n = wn * 32 + p * 16 + ((lane >> 4) << 3) + (lane & 7);
                int k = ks * 16 + (((lane >> 3) & 1) << 3);
                uint32_t off = (uint32_t)(n * RS + k) * 2;
                ldm4(bh[p], sB_hi + off);
                ldm4(bl[p], sB_lo + off);
            }
#pragma unroll
            for (int mf = 0; mf < 2; mf++)
#pragma unroll
                for (int nf = 0; nf < 4; nf++) {
                    const int p = nf >> 1, q = (nf & 1) * 2;
                    mma16816(acc[mf][nf], ah[mf], bh[p][q], bh[p][q + 1]);
                    mma16816(acc[mf][nf], ah[mf], bl[p][q], bl[p][q + 1]);
                    mma16816(acc[mf][nf], al[mf], bh[p][q], bh[p][q + 1]);
                }
        }
        __syncthreads();
    }

#pragma unroll
    for (int mf = 0; mf < 2; mf++)
#pragma unroll
        for (int nf = 0; nf < 4; nf++) {
            int row = bm + wm * 32 + mf * 16 + (lane >> 2);
            int col = bn + wn * 32 + nf * 8 + (lane & 3) * 2;
            *(float2*)&C[(size_t)row * CC + col] =
                make_float2(acc[mf][nf][0], acc[mf][nf][1]);
            *(float2*)&C[(size_t)(row + 8) * CC + col] =
                make_float2(acc[mf][nf][2], acc[mf][nf][3]);
        }
}

// ---------------- stage 2 ----------------
__global__ __launch_bounds__(256) void k_stage2(
    const float* __restrict__ kraw_in,
    const float* __restrict__ hd,   const float* __restrict__ haaa,
    const float* __restrict__ hma,  const float* __restrict__ hmk,
    const float* __restrict__ hkkk, const float* __restrict__ gh,
    const float* __restrict__ td,   const float* __restrict__ dw2,
    const float* __restrict__ taa,  const float* __restrict__ aw2,
    const float* __restrict__ tmisca, const float* __restrict__ maw2,
    const float* __restrict__ tmisck, const float* __restrict__ mkw2,
    const float* __restrict__ kkkw2,  const float* __restrict__ gw2,
    float* __restrict__ decout, float* __restrict__ aout,
    float* __restrict__ kkout,  float* __restrict__ kout, float* __restrict__ gout) {
    const int t0 = blockIdx.x * 8, tid = threadIdx.x;
    __shared__ float shd[8][64];
    __shared__ float sh16[4][8][16];
    __shared__ float shg[8][128];
    for (int i = tid; i < 8 * 64; i += 256)
        shd[i >> 6][i & 63] = hd[(size_t)(t0 + (i >> 6)) * 64 + (i & 63)];
    for (int i = tid; i < 8 * 16; i += 256) {
        int rr = i >> 4, j = i & 15;
        sh16[0][rr][j] = haaa[(size_t)(t0 + rr) * 16 + j];
        sh16[1][rr][j] = hma [(size_t)(t0 + rr) * 16 + j];
        sh16[2][rr][j] = hmk [(size_t)(t0 + rr) * 16 + j];
        sh16[3][rr][j] = hkkk[(size_t)(t0 + rr) * 16 + j];
    }
    for (int i = tid; i < 8 * 128; i += 256)
        shg[i >> 7][i & 127] = gh[(size_t)(t0 + (i >> 7)) * 128 + (i & 127)];
    __syncthreads();

    for (int c = tid; c < CC; c += 256) {
        float ud[8], ua[8], uma[8], umk[8], ukk[8], ug[8];
#pragma unroll
        for (int rr = 0; rr < 8; rr++) { ud[rr]=0.f; ua[rr]=0.f; uma[rr]=0.f; umk[rr]=0.f; ukk[rr]=0.f; ug[rr]=0.f; }
#pragma unroll 8
        for (int j = 0; j < 64; j++) {
            float w = dw2[(size_t)j * CC + c];
#pragma unroll
            for (int rr = 0; rr < 8; rr++) ud[rr] = fmaf(shd[rr][j], w, ud[rr]);
        }
#pragma unroll 4
        for (int j = 0; j < 16; j++) {
            float w1 = aw2[(size_t)j * CC + c],  w2v = maw2[(size_t)j * CC + c];
            float w3 = mkw2[(size_t)j * CC + c], w4  = kkkw2[(size_t)j * CC + c];
#pragma unroll
            for (int rr = 0; rr < 8; rr++) {
                ua[rr]  = fmaf(sh16[0][rr][j], w1,  ua[rr]);
                uma[rr] = fmaf(sh16[1][rr][j], w2v, uma[rr]);
                umk[rr] = fmaf(sh16[2][rr][j], w3,  umk[rr]);
                ukk[rr] = fmaf(sh16[3][rr][j], w4,  ukk[rr]);
            }
        }
#pragma unroll 8
        for (int j = 0; j < 128; j++) {
            float w = gw2[(size_t)j * CC + c];
#pragma unroll
            for (int rr = 0; rr < 8; rr++) ug[rr] = fmaf(shg[rr][j], w, ug[rr]);
        }
        float tdv = td[c], taav = taa[c], tmav = tmisca[c], tmkv = tmisck[c];
#pragma unroll
        for (int rr = 0; rr < 8; rr++) {
            size_t idx = (size_t)(t0 + rr) * CC + c;
            float z  = tdv + ud[rr];
            float wv = -(fmaxf(-z, 0.f) + __logf(1.f + __expf(-fabsf(z)))) - 0.5f;
            decout[idx] = __expf(wv);
            float av  = __fdividef(1.f, 1.f + __expf(-(taav + ua[rr])));
            aout[idx] = av;
            float mav = __fdividef(1.f, 1.f + __expf(-(tmav + uma[rr])));
            float mkv = __fdividef(1.f, 1.f + __expf(-(tmkv + umk[rr])));
            float kr  = kraw_in[idx];
            kkout[idx] = kr + ukk[rr];
            float km = kr * (mav + av * (1.f - mav));
            km *= __expf(fminf(wv * mkv, 0.f));
            kout[idx] = km;
            gout[idx] = ug[rr];
        }
    }
}

// ---------------- kk norm ----------------
__global__ void k_kknorm(float* __restrict__ kk) {
    const int t = blockIdx.x, tid = threadIdx.x;
    const size_t base = (size_t)t * CC + tid * 8;
    float4 a = *(float4*)&kk[base];
    float4 b = *(float4*)&kk[base + 4];
    float ss = a.x*a.x + a.y*a.y + a.z*a.z + a.w*a.w
             + b.x*b.x + b.y*b.y + b.z*b.z + b.w*b.w;
    ss += __shfl_xor_sync(0xffffffffu, ss, 1);
    ss += __shfl_xor_sync(0xffffffffu, ss, 2);
    ss += __shfl_xor_sync(0xffffffffu, ss, 4);
    float inv = __fdividef(1.f, fmaxf(sqrtf(ss), 1e-12f));
    a.x *= inv; a.y *= inv; a.z *= inv; a.w *= inv;
    b.x *= inv; b.y *= inv; b.z *= inv; b.w *= inv;
    *(float4*)&kk[base]     = a;
    *(float4*)&kk[base + 4] = b;
}

// ---------------- WKV7 v4 (R11): pipelined recurrence, interleaved shfl chains -
template <int STEPS>
__global__ __launch_bounds__(256) void k_wkv(
    const float* __restrict__ R, const float* __restrict__ Dec,
    const float* __restrict__ K, const float* __restrict__ Kk,
    const float* __restrict__ Asig, const float* __restrict__ V,
    float* __restrict__ Y) {
    __shared__ __align__(16) float ring[16 * 336];
    const int h = blockIdx.x, rb = blockIdx.y, tid = threadIdx.x;
    const int il = tid >> 4, cg = tid & 15;
    const int rowidx = h * 64 + rb * 16 + il;
    const uint32_t rbase = smem_u32(ring);

    const float* src0 = Dec + h * 64;
    uint32_t doff = 0;
    bool prod = (tid < 84);
    if (tid < 80) {
        int arr = tid >> 4, q = tid & 15;
        const float* base = (arr == 0) ? Dec : (arr == 1) ? K : (arr == 2) ? Kk
                          : (arr == 3) ? R : Asig;
        src0 = base + h * 64 + q * 4;
        doff = (uint32_t)(arr * 64 + q * 4) * 4;
    } else if (tid < 84) {
        src0 = V + h * 64 + rb * 16 + (tid - 80) * 4;
        doff = (uint32_t)(320 + (tid - 80) * 4) * 4;
    }

    auto issueB = [&](int t0) {
        if (prod) {
#pragma unroll
            for (int j = 0; j < 4; j++) {
                int ts = t0 + j; if (ts > STEPS - 1) ts = STEPS - 1;
                CPA16(rbase + (uint32_t)(((t0 + j) & 15) * 1344) + doff,
                      src0 + (size_t)ts * CC);
            }
        }
        CPA_COMMIT();
    };

    issueB(0); issueB(4); issueB(8);
    asm volatile("cp.async.wait_group 1;" ::: "memory");
    __syncthreads();

    float4 cd, ck, cq, cr, ca; float cvi;
    {
        const float* st = ring;
        cd = ((const float4*)(st))[cg];
        ck = ((const float4*)(st + 64))[cg];
        cq = ((const float4*)(st + 128))[cg];
        cr = ((const float4*)(st + 192))[cg];
        ca = ((const float4*)(st + 256))[cg];
        cvi = st[320 + il];
    }

    float4 s4 = make_float4(0.f, 0.f, 0.f, 0.f);
    float sa = 0.f;

#pragma unroll 1
    for (int t0 = 0; t0 < STEPS; t0 += 4) {
        issueB(t0 + 12);
#pragma unroll
        for (int d = 0; d < 4; d++) {
            const int t = t0 + d;
            const float* sn = ring + ((t + 1) & 15) * 336;
            float4 nd = ((const float4*)(sn))[cg];
            float4 nk = ((const float4*)(sn + 64))[cg];
            float4 nq = ((const float4*)(sn + 128))[cg];
            float4 nr = ((const float4*)(sn + 192))[cg];
            float4 na = ((const float4*)(sn + 256))[cg];
            float  nvi = sn[320 + il];

            s4.x = fmaf(cvi, ck.x, fmaf(sa, cq.x * ca.x, s4.x * cd.x));
            s4.y = fmaf(cvi, ck.y, fmaf(sa, cq.y * ca.y, s4.y * cd.y));
            s4.z = fmaf(cvi, ck.z, fmaf(sa, cq.z * ca.z, s4.z * cd.z));
            s4.w = fmaf(cvi, ck.w, fmaf(sa, cq.w * ca.w, s4.w * cd.w));

            float o  = s4.x * cr.x + s4.y * cr.y + s4.z * cr.z + s4.w * cr.w;
            float sv = s4.x * nq.x + s4.y * nq.y + s4.z * nq.z + s4.w * nq.w;
            o  += __shfl_xor_sync(0xffffffffu, o, 1);
            sv += __shfl_xor_sync(0xffffffffu, sv, 1);
            o  += __shfl_xor_sync(0xffffffffu, o, 2);
            sv += __shfl_xor_sync(0xffffffffu, sv, 2);
            o  += __shfl_xor_sync(0xffffffffu, o, 4);
            sv += __shfl_xor_sync(0xffffffffu, sv, 4);
            o  += __shfl_xor_sync(0xffffffffu, o, 8);
            sv += __shfl_xor_sync(0xffffffffu, sv, 8);
            if (cg == 0) Y[(size_t)t * CC + rowidx] = o;

            sa = -sv;
            cd = nd; ck = nk; cq = nq; cr = nr; ca = na; cvi = nvi;
        }
        asm volatile("cp.async.wait_group 1;" ::: "memory");
        __syncthreads();
    }
}

// ---------------- groupnorm + bonus + gate -> bf16 hi/lo ----------------
__global__ __launch_bounds__(512) void k_gn(
    const float* __restrict__ Yin, const float* __restrict__ R,
    const float* __restrict__ K,   const float* __restrict__ V,
    const float* __restrict__ G,   const float* __restrict__ faaaa,
    const float* __restrict__ lnw, const float* __restrict__ lnb,
    __nv_bfloat16* __restrict__ ymhi, __nv_bfloat16* __restrict__ ymlo) {
    const int t = blockIdx.x, tid = threadIdx.x;
    const int c = tid * 4;
    const size_t idx = (size_t)t * CC + c;
    float4 y  = *(const float4*)&Yin[idx];
    float4 r4 = *(const float4*)&R[idx];
    float4 k4 = *(const float4*)&K[idx];
    float4 v4 = *(const float4*)&V[idx];
    float4 g4 = *(const float4*)&G[idx];
    float4 f4 = *(const float4*)&faaaa[c];
    float4 w4 = *(const float4*)&lnw[c];
    float4 b4 = *(const float4*)&lnb[c];

    float s1 = y.x + y.y + y.z + y.w;
    float s2 = y.x*y.x + y.y*y.y + y.z*y.z + y.w*y.w;
    float s3 = r4.x*k4.x*f4.x + r4.y*k4.y*f4.y + r4.z*k4.z*f4.z + r4.w*k4.w*f4.w;
#pragma unroll
    for (int m = 1; m <= 8; m <<= 1) {
        s1 += __shfl_xor_sync(0xffffffffu, s1, m);
        s2 += __shfl_xor_sync(0xffffffffu, s2, m);
        s3 += __shfl_xor_sync(0xffffffffu, s3, m);
    }
    float mu  = s1 * (1.f / 64.f);
    float var = s2 * (1.f / 64.f) - mu * mu;
    float rs  = rsqrtf(var + EPSGN);
    float o[4];
    o[0] = (fmaf((y.x - mu) * rs, w4.x, b4.x) + s3 * v4.x) * g4.x;
    o[1] = (fmaf((y.y - mu) * rs, w4.y, b4.y) + s3 * v4.y) * g4.y;
    o[2] = (fmaf((y.z - mu) * rs, w4.z, b4.z) + s3 * v4.z) * g4.z;
    o[3] = (fmaf((y.w - mu) * rs, w4.w, b4.w) + s3 * v4.w) * g4.w;
    __nv_bfloat16 hh[4], ll[4];
#pragma unroll
    for (int q = 0; q < 4; q++) {
        hh[q] = __float2bfloat16(o[q]);
        ll[q] = __float2bfloat16(o[q] - __bfloat162float(hh[q]));
    }
    *(uint2*)&ymhi[idx] = *(uint2*)hh;
    *(uint2*)&ymlo[idx] = *(uint2*)ll;
}

// ---------------------------------------------------------------------------
extern "C" void kernel_launch(void* const* d_in, const int* in_sizes, int n_in,
                              void* d_out, int out_size) {
    const float* x      = (const float*)d_in[0];
    const float* Wq     = (const float*)d_in[1];
    const float* Wk     = (const float*)d_in[2];
    const float* Wv     = (const float*)d_in[3];
    const float* Wo     = (const float*)d_in[4];
    const float* tmx    = (const float*)d_in[5];
    const float* tmrg   = (const float*)d_in[6];
    const float* tmwa   = (const float*)d_in[7];
    const float* tmk    = (const float*)d_in[8];
    const float* tmv    = (const float*)d_in[9];
    const float* maa_w1 = (const float*)d_in[10];
    const float* maa_w2 = (const float*)d_in[11];
    const float* tdecay = (const float*)d_in[12];
    const float* dw1    = (const float*)d_in[13];
    const float* dw2    = (const float*)d_in[14];
    const float* taaaaa = (const float*)d_in[15];
    const float* aaa_w1 = (const float*)d_in[16];
    const float* aaa_w2 = (const float*)d_in[17];
    const float* kkk_w1 = (const float*)d_in[18];
    const float* kkk_w2 = (const float*)d_in[19];
    const float* gate_w1 = (const float*)d_in[20];
    const float* gate_w2 = (const float*)d_in[21];
    const float* tmisca = (const float*)d_in[22];
    const float* ma_w1  = (const float*)d_in[23];
    const float* ma_w2  = (const float*)d_in[24];
    const float* tmisck = (const float*)d_in[25];
    const float* mk_w1  = (const float*)d_in[26];
    const float* mk_w2  = (const float*)d_in[27];
    const float* faaaa  = (const float*)d_in[28];
    const float* lnw    = (const float*)d_in[29];
    const float* lnb    = (const float*)d_in[30];
    float* out = (float*)d_out;

    float* S = nullptr;
    cudaGetSymbolAddress((void**)&S, g_scratch);
    __nv_bfloat16* BF = nullptr;
    cudaGetSymbolAddress((void**)&BF, g_bf);

    float* dxp  = S + O_DXP;  float* xxx  = S + O_XXX;
    float* xrg  = S + O_XRG;  float* xwa  = S + O_XWA;
    float* xk   = S + O_XK;   float* xv   = S + O_XV;
    float* R    = S + O_R;    float* Kraw = S + O_KRAW;
    float* V    = S + O_V;    float* Dec  = S + O_DEC;
    float* A    = S + O_A;    float* KK   = S + O_KK;
    float* K    = S + O_K;    float* G    = S + O_G;
    float* Y    = S + O_Y;
    float* hmix = S + O_HMIX; float* gh   = S + O_GH;
    float* hd   = S + O_HD;   float* haaa = S + O_HAAA;
    float* hma  = S + O_HMA;  float* hmk  = S + O_HMK;
    float* hkkk = S + O_HKKK;

    __nv_bfloat16* Wbuf[4][2];
    for (int i = 0; i < 4; i++) {
        Wbuf[i][0] = BF + (size_t)i * 2 * CC * CC;
        Wbuf[i][1] = Wbuf[i][0] + (size_t)CC * CC;
    }
    __nv_bfloat16* Abase = BF + 8ull * CC * CC;
    __nv_bfloat16* ArgH = Abase + 0ull * TC; __nv_bfloat16* ArgL = Abase + 1ull * TC;
    __nv_bfloat16* AkH  = Abase + 2ull * TC; __nv_bfloat16* AkL  = Abase + 3ull * TC;
    __nv_bfloat16* AvH  = Abase + 4ull * TC; __nv_bfloat16* AvL  = Abase + 5ull * TC;
    __nv_bfloat16* AyH  = Abase + 6ull * TC; __nv_bfloat16* AyL  = Abase + 7ull * TC;

    cudaFuncSetAttribute(k_bigmm, cudaFuncAttributeMaxDynamicSharedMemorySize, GM_SMEM);
    const int PS128 = 2 * (64 * 128 + 512) * 4;
    const int PS64  = 2 * (64 * 64  + 512) * 4;
    const int PS32  = 2 * (64 * 32  + 512) * 4;
    cudaFuncSetAttribute((const void*)k_proj<128,128,1,0>, cudaFuncAttributeMaxDynamicSharedMemorySize, PS128);
    cudaFuncSetAttribute((const void*)k_proj<64,64,1,0>,   cudaFuncAttributeMaxDynamicSharedMemorySize, PS64);
    cudaFuncSetAttribute((const void*)k_proj<32,16,0,0>,   cudaFuncAttributeMaxDynamicSharedMemorySize, PS32);
    cudaFuncSetAttribute((const void*)k_proj<32,16,0,1>,   cudaFuncAttributeMaxDynamicSharedMemorySize, PS32);

    dim3 mg(CC / 64, TT / 128);   // 32 x 8 = 256 CTAs

    // 1: tokshift + all weight preps
    k_init<<<8192 + 16384, 256>>>(x, tmx, dxp, xxx, Wq, Wk, Wv, Wo, BF);
    // 2
    k_proj<128,128,1,0><<<TT / 8, 256, PS128>>>(xxx, maa_w1, maa_w1, hmix, hmix);
    // 3
    k_mix_apply<<<dim3(CC / 128, TT / 8, 4), 128>>>(x, dxp, hmix, maa_w2,
                                                    tmrg, tmwa, tmk, tmv,
                                                    xrg, xwa, xk, xv,
                                                    ArgH, ArgL, AkH, AkL, AvH, AvL);
    // 4 (ncu capture slot), 5, 6: QKV GEMMs
    k_bigmm<<<mg, 256, GM_SMEM>>>(ArgH, ArgL, Wbuf[0][0], Wbuf[0][1], R);
    k_bigmm<<<mg, 256, GM_SMEM>>>(AkH, AkL, Wbuf[1][0], Wbuf[1][1], Kraw);
    k_bigmm<<<mg, 256, GM_SMEM>>>(AvH, AvL, Wbuf[2][0], Wbuf[2][1], V);

    k_proj<128,128,1,0><<<TT / 8, 256, PS128>>>(xrg, gate_w1, gate_w1, gh, gh);
    k_proj<64,64,1,0>  <<<TT / 8, 256, PS64 >>>(xwa, dw1, dw1, hd, hd);
    k_proj<32,16,0,0>  <<<TT / 8, 256, PS32 >>>(xwa, aaa_w1, ma_w1, haaa, hma);
    k_proj<32,16,0,1>  <<<TT / 8, 256, PS32 >>>(xk,  mk_w1, kkk_w1, hmk, hkkk);

    k_stage2<<<TT / 8, 256>>>(Kraw, hd, haaa, hma, hmk, hkkk, gh,
                              tdecay, dw2, taaaaa, aaa_w2, tmisca, ma_w2,
                              tmisck, mk_w2, kkk_w2, gate_w2,
                              Dec, A, KK, K, G);
    k_kknorm<<<TT, 256>>>(KK);
    k_wkv<TT><<<dim3(HH, 4), 256>>>(R, Dec, K, KK, A, V, Y);
    k_gn<<<TT, 512>>>(Y, R, K, V, G, faaaa, lnw, lnb, AyH, AyL);
    k_bigmm<<<mg, 256, GM_SMEM>>>(AyH, AyL, Wbuf[3][0], Wbuf[3][1], out);
}

// round 16
// speedup vs baseline: 1.0790x; 1.0790x over previous
#include <cuda_runtime.h>
#include <cuda_bf16.h>
#include <math.h>
#include <stdint.h>

#define TT 1024
#define CC 2048
#define HH 32
#define TC (TT*CC)
#define EPSGN 0.00064f

// ---------------- scratch ----------------
__device__ __align__(128) float g_scratch[16ull*TC + 2ull*TT*128 + (size_t)TT*64 + 4ull*TT*16];
__device__ __align__(128) __nv_bfloat16 g_bf[8ull*CC*CC + 8ull*TT*CC];

#define O_DXP   ((size_t)0*TC)
#define O_XXX   ((size_t)1*TC)
#define O_XRG   ((size_t)2*TC)
#define O_XWA   ((size_t)3*TC)
#define O_XK    ((size_t)4*TC)
#define O_XV    ((size_t)5*TC)
#define O_R     ((size_t)6*TC)
#define O_KRAW  ((size_t)7*TC)
#define O_V     ((size_t)8*TC)
#define O_DEC   ((size_t)9*TC)
#define O_A     ((size_t)10*TC)
#define O_KK    ((size_t)11*TC)
#define O_K     ((size_t)12*TC)
#define O_G     ((size_t)13*TC)
#define O_Y     ((size_t)14*TC)
#define O_HMIX  ((size_t)16*TC)
#define O_GH    (O_HMIX + (size_t)TT*128)
#define O_HD    (O_GH   + (size_t)TT*128)
#define O_HAAA  (O_HD   + (size_t)TT*64)
#define O_HMA   (O_HAAA + (size_t)TT*16)
#define O_HMK   (O_HMA  + (size_t)TT*16)
#define O_HKKK  (O_HMK  + (size_t)TT*16)

// ---------------- helpers ----------------
__device__ __forceinline__ uint32_t smem_u32(const void* p) {
    uint32_t a;
    asm("{ .reg .u64 t; cvta.to.shared.u64 t, %1; cvt.u32.u64 %0, t; }" : "=r"(a) : "l"(p));
    return a;
}
__device__ __forceinline__ void ldm4(uint32_t r[4], uint32_t a) {
    asm volatile("ldmatrix.sync.aligned.m8n8.x4.shared.b16 {%0,%1,%2,%3}, [%4];"
                 : "=r"(r[0]), "=r"(r[1]), "=r"(r[2]), "=r"(r[3]) : "r"(a));
}
__device__ __forceinline__ void mma16816(float c[4], const uint32_t a[4], uint32_t b0, uint32_t b1) {
    asm volatile("mma.sync.aligned.m16n8k16.row.col.f32.bf16.bf16.f32 "
                 "{%0,%1,%2,%3},{%4,%5,%6,%7},{%8,%9},{%0,%1,%2,%3};"
                 : "+f"(c[0]), "+f"(c[1]), "+f"(c[2]), "+f"(c[3])
                 : "r"(a[0]), "r"(a[1]), "r"(a[2]), "r"(a[3]), "r"(b0), "r"(b1));
}
#define CPA16(dst, src) asm volatile("cp.async.ca.shared.global [%0], [%1], 16;" :: "r"(dst), "l"(src))
#define CPA4(dst, src)  asm volatile("cp.async.ca.shared.global [%0], [%1], 4;"  :: "r"(dst), "l"(src))
#define CPA_COMMIT() asm volatile("cp.async.commit_group;" ::: "memory")

// ---------------- k_init: tokshift + wprep x4 ----------------
__global__ void k_init(const float* __restrict__ x, const float* __restrict__ maa_x,
                       float* __restrict__ dxp, float* __restrict__ xxx,
                       const float* __restrict__ Wq, const float* __restrict__ Wk,
                       const float* __restrict__ Wv, const float* __restrict__ Wo,
                       __nv_bfloat16* __restrict__ BF) {
    const int bid = blockIdx.x, tid = threadIdx.x;
    if (bid < 8192) {
        int idx = bid * 256 + tid;
        int t = idx >> 11, c = idx & (CC - 1);
        float xv = x[idx];
        float pv = (t > 0) ? x[idx - CC] : 0.0f;
        float dx = pv - xv;
        dxp[idx] = dx;
        xxx[idx] = fmaf(dx, maa_x[c], xv);
        return;
    }
    __shared__ float tl[32][33];
    const int wb = bid - 8192;
    const int widx = wb >> 12;
    const int tile = wb & 4095;
    const float* W = (widx == 0) ? Wq : (widx == 1) ? Wk : (widx == 2) ? Wv : Wo;
    __nv_bfloat16* Thi = BF + (size_t)widx * 2 * CC * CC;
    __nv_bfloat16* Tlo = Thi + (size_t)CC * CC;
    const int n0 = (tile & 63) * 32, k0 = (tile >> 6) * 32;
    const int tx = tid & 31, ty = tid >> 5;
#pragma unroll
    for (int j = 0; j < 4; j++)
        tl[ty + j * 8][tx] = W[(size_t)(k0 + ty + j * 8) * CC + n0 + tx];
    __syncthreads();
#pragma unroll
    for (int j = 0; j < 4; j++) {
        float v = tl[tx][ty + j * 8];
        __nv_bfloat16 h = __float2bfloat16(v);
        size_t o = (size_t)(n0 + ty + j * 8) * CC + k0 + tx;
        Thi[o] = h;
        Tlo[o] = __float2bfloat16(v - __bfloat162float(h));
    }
}

// ---------------- k_proj ----------------
template <int NN, int SPLIT, int ACT0, int ACT1>
__global__ __launch_bounds__(256) void k_proj(const float* __restrict__ A,
                                              const float* __restrict__ W0,
                                              const float* __restrict__ W1,
                                              float* __restrict__ out0,
                                              float* __restrict__ out1) {
    constexpr int G = 256 / NN;
    constexpr int R = 8 / G;
    constexpr int WCH = 64 * NN;
    extern __shared__ __align__(16) float psm[];
    float* Ws = psm;
    float* As = psm + 2 * WCH;
    const uint32_t ws_b = smem_u32(Ws);
    const uint32_t as_b = smem_u32(As);

    const int tid = threadIdx.x;
    const int n = tid % NN, g = tid / NN;
    const int r0 = blockIdx.x * 8;

    auto load_stage = [&](int kc, int stg) {
#pragma unroll
        for (int j = 0; j < WCH / 1024; j++) {
            int i = (tid + j * 256) * 4;
            int row = i / NN, col = i % NN;
            const float* src = (col < SPLIT)
                ? (W0 + (size_t)(kc + row) * SPLIT + col)
                : (W1 + (size_t)(kc + row) * (NN - SPLIT) + (col - SPLIT));
            CPA16(ws_b + (uint32_t)(stg * WCH + i) * 4, src);
        }
#pragma unroll
        for (int j = 0; j < 2; j++) {
            int i = tid + j * 256;
            int row = i >> 6, k = i & 63;
            CPA4(as_b + (uint32_t)(stg * 512 + k * 8 + row) * 4,
                 A + (size_t)(r0 + row) * CC + kc + k);
        }
        CPA_COMMIT();
    };

    float acc[R];
#pragma unroll
    for (int i = 0; i < R; i++) acc[i] = 0.f;

    load_stage(0, 0);
    for (int ch = 0; ch < 32; ch++) {
        const int b = ch & 1;
        if (ch + 1 < 32) {
            load_stage((ch + 1) * 64, b ^ 1);
            asm volatile("cp.async.wait_group 1;" ::: "memory");
        } else {
            asm volatile("cp.async.wait_group 0;" ::: "memory");
        }
        __syncthreads();
        const float* ws = Ws + b * WCH;
        const float* as = As + b * 512;
#pragma unroll 8
        for (int k = 0; k < 64; k++) {
            float wv = ws[k * NN + n];
            if (R == 4) {
                float4 a4 = *(const float4*)&as[k * 8 + g * 4];
                acc[0] = fmaf(a4.x, wv, acc[0]);
                acc[1] = fmaf(a4.y, wv, acc[1]);
                acc[2] = fmaf(a4.z, wv, acc[2]);
                acc[3] = fmaf(a4.w, wv, acc[3]);
            } else if (R == 2) {
                float2 a2 = *(const float2*)&as[k * 8 + g * 2];
                acc[0] = fmaf(a2.x, wv, acc[0]);
                acc[1] = fmaf(a2.y, wv, acc[1]);
            } else {
                acc[0] = fmaf(as[k * 8 + g], wv, acc[0]);
            }
        }
        __syncthreads();
    }

#pragma unroll
    for (int i = 0; i < R; i++) {
        int row = r0 + g * R + i;
        float v = acc[i];
        if (n < SPLIT) {
            if (ACT0) v = tanhf(v);
            out0[(size_t)row * SPLIT + n] = v;
        } else {
            if (ACT1) v = tanhf(v);
            out1[(size_t)row * (NN - SPLIT) + (n - SPLIT)] = v;
        }
    }
}

// ---------------- mix apply (+ bf16 hi/lo emission) ----------------
__global__ void k_mix_apply(const float* __restrict__ x, const float* __restrict__ dxp,
                            const float* __restrict__ hmix, const float* __restrict__ w2full,
                            const float* __restrict__ tm0, const float* __restrict__ tm1,
                            const float* __restrict__ tm2, const float* __restrict__ tm3,
                            float* __restrict__ o0, float* __restrict__ o1,
                            float* __restrict__ o2, float* __restrict__ o3,
                            __nv_bfloat16* __restrict__ bh0, __nv_bfloat16* __restrict__ bl0,
                            __nv_bfloat16* __restrict__ bh2, __nv_bfloat16* __restrict__ bl2,
                            __nv_bfloat16* __restrict__ bh3, __nv_bfloat16* __restrict__ bl3) {
    const int f = blockIdx.z, t0 = blockIdx.y * 8;
    const int c = blockIdx.x * 128 + threadIdx.x;
    __shared__ float hm[8][32];
    for (int i = threadIdx.x; i < 8 * 32; i += 128) {
        int tt = i >> 5, d = i & 31;
        hm[tt][d] = hmix[(size_t)(t0 + tt) * 128 + f * 32 + d];
    }
    __syncthreads();
    const float* w2 = w2full + (size_t)f * 32 * CC;
    float acc[8];
#pragma unroll
    for (int i = 0; i < 8; i++) acc[i] = 0.f;
#pragma unroll 8
    for (int d = 0; d < 32; d++) {
        float wv = w2[(size_t)d * CC + c];
#pragma unroll
        for (int tt = 0; tt < 8; tt++) acc[tt] = fmaf(hm[tt][d], wv, acc[tt]);
    }
    const float* tm  = (f == 0) ? tm0 : (f == 1) ? tm1 : (f == 2) ? tm2 : tm3;
    float*       out = (f == 0) ? o0  : (f == 1) ? o1  : (f == 2) ? o2  : o3;
    __nv_bfloat16* ph = (f == 0) ? bh0 : (f == 2) ? bh2 : (f == 3) ? bh3 : nullptr;
    __nv_bfloat16* pl = (f == 0) ? bl0 : (f == 2) ? bl2 : (f == 3) ? bl3 : nullptr;
    float tmv = tm[c];
#pragma unroll
    for (int tt = 0; tt < 8; tt++) {
        size_t idx = (size_t)(t0 + tt) * CC + c;
        float v = fmaf(dxp[idx], tmv + acc[tt], x[idx]);
        out[idx] = v;
        if (f != 1) {
            __nv_bfloat16 h = __float2bfloat16(v);
            ph[idx] = h;
            pl[idx] = __float2bfloat16(v - __bfloat162float(h));
        }
    }
}

// ---------------- mma.sync split-bf16 GEMM (K-chunk 64, RS 72, 144KB) ----------
#define RS 72
#define TILE_H (128 * RS)
#define STAGE_H (4 * TILE_H)
#define GM_SMEM (2 * STAGE_H * 2)
__global__ __launch_bounds__(256) void k_bigmm(
    const __nv_bfloat16* __restrict__ Ahi, const __nv_bfloat16* __restrict__ Alo,
    const __nv_bfloat16* __restrict__ Bhi, const __nv_bfloat16* __restrict__ Blo,
    float* __restrict__ C) {
    extern __shared__ __align__(16) __nv_bfloat16 sm[];
    const int tid = threadIdx.x, wid = tid >> 5, lane = tid & 31;
    const int bn = blockIdx.x * 128, bm = blockIdx.y * 128;
    const int wm = wid & 1, wn = wid >> 1;
    const uint32_t sb = smem_u32(sm);

    const __nv_bfloat16* gsrc[4] = {
        Ahi + (size_t)bm * CC, Alo + (size_t)bm * CC,
        Bhi + (size_t)bn * CC, Blo + (size_t)bn * CC };

    float acc[4][4][4];
#pragma unroll
    for (int a = 0; a < 4; a++)
#pragma unroll
        for (int b = 0; b < 4; b++)
#pragma unroll
            for (int c = 0; c < 4; c++) acc[a][b][c] = 0.f;

    const int lr = tid >> 3, ls = tid & 7;
    auto load_stage = [&](int kc, int stg) {
#pragma unroll
        for (int tl = 0; tl < 4; tl++) {
            const __nv_bfloat16* s = gsrc[tl] + kc;
            uint32_t d = sb + (uint32_t)(stg * STAGE_H + tl * TILE_H) * 2;
#pragma unroll
            for (int j = 0; j < 4; j++) {
                int rr = lr + j * 32;
                CPA16(d + (uint32_t)(rr * RS + ls * 8) * 2, s + (size_t)rr * CC + ls * 8);
            }
        }
        CPA_COMMIT();
    };

    const int KT = CC / 64;
    load_stage(0, 0);

    for (int kt = 0; kt < KT; kt++) {
        const int stg = kt & 1;
        if (kt + 1 < KT) {
            load_stage((kt + 1) * 64, stg ^ 1);
            asm volatile("cp.async.wait_group 1;" ::: "memory");
        } else {
            asm volatile("cp.async.wait_group 0;" ::: "memory");
        }
        __syncthreads();

        const uint32_t sA_hi = sb + (uint32_t)(stg * STAGE_H + 0 * TILE_H) * 2;
        const uint32_t sA_lo = sb + (uint32_t)(stg * STAGE_H + 1 * TILE_H) * 2;
        const uint32_t sB_hi = sb + (uint32_t)(stg * STAGE_H + 2 * TILE_H) * 2;
        const uint32_t sB_lo = sb + (uint32_t)(stg * STAGE_H + 3 * TILE_H) * 2;

#pragma unroll
        for (int ks = 0; ks < 4; ks++) {
            uint32_t ah[4][4], al[4][4], bh[2][4], bl[2][4];
#pragma unroll
            for (int mf = 0; mf < 4; mf++) {
                int row = wm * 64 + mf * 16 + (lane & 15);
                int col = ks * 16 + ((lane >> 4) << 3);
                uint32_t off = (uint32_t)(row * RS + col) * 2;
                ldm4(ah[mf], sA_hi + off);
                ldm4(al[mf], sA_lo + off);
            }
#pragma unroll
            for (int p = 0; p < 2; p++) {
                int n = wn * 32 + p * 16 + ((lane >> 4) << 3) + (lane & 7);
                int k = ks * 16 + (((lane >> 3) & 1) << 3);
                uint32_t off = (uint32_t)(n * RS + k) * 2;
                ldm4(bh[p], sB_hi + off);
                ldm4(bl[p], sB_lo + off);
            }
#pragma unroll
            for (int mf = 0; mf < 4; mf++)
#pragma unroll
                for (int nf = 0; nf < 4; nf++) {
                    const int p = nf >> 1, q = (nf & 1) * 2;
                    mma16816(acc[mf][nf], ah[mf], bh[p][q], bh[p][q + 1]);
                    mma16816(acc[mf][nf], ah[mf], bl[p][q], bl[p][q + 1]);
                    mma16816(acc[mf][nf], al[mf], bh[p][q], bh[p][q + 1]);
                }
        }
        __syncthreads();
    }

#pragma unroll
    for (int mf = 0; mf < 4; mf++)
#pragma unroll
        for (int nf = 0; nf < 4; nf++) {
            int row = bm + wm * 64 + mf * 16 + (lane >> 2);
            int col = bn + wn * 32 + nf * 8 + (lane & 3) * 2;
            *(float2*)&C[(size_t)row * CC + col] =
                make_float2(acc[mf][nf][0], acc[mf][nf][1]);
            *(float2*)&C[(size_t)(row + 8) * CC + col] =
                make_float2(acc[mf][nf][2], acc[mf][nf][3]);
        }
}

// ---------------- stage 2 (+ fused kk norm), dynamic smem ----------------
// smem floats: shd 512 | sh16 512 | shg 1024 | kkbuf 16384 | invbuf 256
#define S2_SMEM ((512 + 512 + 1024 + 16384 + 256) * 4)
__global__ __launch_bounds__(256) void k_stage2(
    const float* __restrict__ kraw_in,
    const float* __restrict__ hd,   const float* __restrict__ haaa,
    const float* __restrict__ hma,  const float* __restrict__ hmk,
    const float* __restrict__ hkkk, const float* __restrict__ gh,
    const float* __restrict__ td,   const float* __restrict__ dw2,
    const float* __restrict__ taa,  const float* __restrict__ aw2,
    const float* __restrict__ tmisca, const float* __restrict__ maw2,
    const float* __restrict__ tmisck, const float* __restrict__ mkw2,
    const float* __restrict__ kkkw2,  const float* __restrict__ gw2,
    float* __restrict__ decout, float* __restrict__ aout,
    float* __restrict__ kkout,  float* __restrict__ kout, float* __restrict__ gout) {
    extern __shared__ __align__(16) float s2m[];
    float (*shd)[64]      = (float(*)[64])s2m;                 // 512
    float (*sh16)[8][16]  = (float(*)[8][16])(s2m + 512);      // 512
    float (*shg)[128]     = (float(*)[128])(s2m + 1024);       // 1024
    float (*kkbuf)[2048]  = (float(*)[2048])(s2m + 2048);      // 16384
    float (*invbuf)[32]   = (float(*)[32])(s2m + 18432);       // 256

    const int t0 = blockIdx.x * 8, tid = threadIdx.x;
    for (int i = tid; i < 8 * 64; i += 256)
        shd[i >> 6][i & 63] = hd[(size_t)(t0 + (i >> 6)) * 64 + (i & 63)];
    for (int i = tid; i < 8 * 16; i += 256) {
        int rr = i >> 4, j = i & 15;
        sh16[0][rr][j] = haaa[(size_t)(t0 + rr) * 16 + j];
        sh16[1][rr][j] = hma [(size_t)(t0 + rr) * 16 + j];
        sh16[2][rr][j] = hmk [(size_t)(t0 + rr) * 16 + j];
        sh16[3][rr][j] = hkkk[(size_t)(t0 + rr) * 16 + j];
    }
    for (int i = tid; i < 8 * 128; i += 256)
        shg[i >> 7][i & 127] = gh[(size_t)(t0 + (i >> 7)) * 128 + (i & 127)];
    __syncthreads();

    for (int c = tid; c < CC; c += 256) {
        float ud[8], ua[8], uma[8], umk[8], ukk[8], ug[8];
#pragma unroll
        for (int rr = 0; rr < 8; rr++) { ud[rr]=0.f; ua[rr]=0.f; uma[rr]=0.f; umk[rr]=0.f; ukk[rr]=0.f; ug[rr]=0.f; }
#pragma unroll 8
        for (int j = 0; j < 64; j++) {
            float w = dw2[(size_t)j * CC + c];
#pragma unroll
            for (int rr = 0; rr < 8; rr++) ud[rr] = fmaf(shd[rr][j], w, ud[rr]);
        }
#pragma unroll 4
        for (int j = 0; j < 16; j++) {
            float w1 = aw2[(size_t)j * CC + c],  w2v = maw2[(size_t)j * CC + c];
            float w3 = mkw2[(size_t)j * CC + c], w4  = kkkw2[(size_t)j * CC + c];
#pragma unroll
            for (int rr = 0; rr < 8; rr++) {
                ua[rr]  = fmaf(sh16[0][rr][j], w1,  ua[rr]);
                uma[rr] = fmaf(sh16[1][rr][j], w2v, uma[rr]);
                umk[rr] = fmaf(sh16[2][rr][j], w3,  umk[rr]);
                ukk[rr] = fmaf(sh16[3][rr][j], w4,  ukk[rr]);
            }
        }
#pragma unroll 8
        for (int j = 0; j < 128; j++) {
            float w = gw2[(size_t)j * CC + c];
#pragma unroll
            for (int rr = 0; rr < 8; rr++) ug[rr] = fmaf(shg[rr][j], w, ug[rr]);
        }
        float tdv = td[c], taav = taa[c], tmav = tmisca[c], tmkv = tmisck[c];
#pragma unroll
        for (int rr = 0; rr < 8; rr++) {
            size_t idx = (size_t)(t0 + rr) * CC + c;
            float z  = tdv + ud[rr];
            float wv = -(fmaxf(-z, 0.f) + __logf(1.f + __expf(-fabsf(z)))) - 0.5f;
            decout[idx] = __expf(wv);
            float av  = __fdividef(1.f, 1.f + __expf(-(taav + ua[rr])));
            aout[idx] = av;
            float mav = __fdividef(1.f, 1.f + __expf(-(tmav + uma[rr])));
            float mkv = __fdividef(1.f, 1.f + __expf(-(tmkv + umk[rr])));
            float kr  = kraw_in[idx];
            kkbuf[rr][c] = kr + ukk[rr];
            float km = kr * (mav + av * (1.f - mav));
            km *= __expf(fminf(wv * mkv, 0.f));
            kout[idx] = km;
            gout[idx] = ug[rr];
        }
    }
    __syncthreads();
    // per-(row, head) sumsq with skewed index (conflict-free)
    {
        int rr = tid >> 5, hh = tid & 31;
        float ss = 0.f;
#pragma unroll 8
        for (int j = 0; j < 64; j++) {
            int jj = (j + hh) & 63;
            float v = kkbuf[rr][hh * 64 + jj];
            ss = fmaf(v, v, ss);
        }
        invbuf[rr][hh] = __fdividef(1.f, fmaxf(sqrtf(ss), 1e-12f));
    }
    __syncthreads();
    for (int c = tid; c < CC; c += 256) {
#pragma unroll
        for (int rr = 0; rr < 8; rr++)
            kkout[(size_t)(t0 + rr) * CC + c] = kkbuf[rr][c] * invbuf[rr][c >> 6];
    }
}

// ---------------- WKV7 v4 (R11): pipelined recurrence, interleaved shfl chains -
template <int STEPS>
__global__ __launch_bounds__(256) void k_wkv(
    const float* __restrict__ R, const float* __restrict__ Dec,
    const float* __restrict__ K, const float* __restrict__ Kk,
    const float* __restrict__ Asig, const float* __restrict__ V,
    float* __restrict__ Y) {
    __shared__ __align__(16) float ring[16 * 336];
    const int h = blockIdx.x, rb = blockIdx.y, tid = threadIdx.x;
    const int il = tid >> 4, cg = tid & 15;
    const int rowidx = h * 64 + rb * 16 + il;
    const uint32_t rbase = smem_u32(ring);

    const float* src0 = Dec + h * 64;
    uint32_t doff = 0;
    bool prod = (tid < 84);
    if (tid < 80) {
        int arr = tid >> 4, q = tid & 15;
        const float* base = (arr == 0) ? Dec : (arr == 1) ? K : (arr == 2) ? Kk
                          : (arr == 3) ? R : Asig;
        src0 = base + h * 64 + q * 4;
        doff = (uint32_t)(arr * 64 + q * 4) * 4;
    } else if (tid < 84) {
        src0 = V + h * 64 + rb * 16 + (tid - 80) * 4;
        doff = (uint32_t)(320 + (tid - 80) * 4) * 4;
    }

    auto issueB = [&](int t0) {
        if (prod) {
#pragma unroll
            for (int j = 0; j < 4; j++) {
                int ts = t0 + j; if (ts > STEPS - 1) ts = STEPS - 1;
                CPA16(rbase + (uint32_t)(((t0 + j) & 15) * 1344) + doff,
                      src0 + (size_t)ts * CC);
            }
        }
        CPA_COMMIT();
    };

    issueB(0); issueB(4); issueB(8);
    asm volatile("cp.async.wait_group 1;" ::: "memory");
    __syncthreads();

    float4 cd, ck, cq, cr, ca; float cvi;
    {
        const float* st = ring;
        cd = ((const float4*)(st))[cg];
        ck = ((const float4*)(st + 64))[cg];
        cq = ((const float4*)(st + 128))[cg];
        cr = ((const float4*)(st + 192))[cg];
        ca = ((const float4*)(st + 256))[cg];
        cvi = st[320 + il];
    }

    float4 s4 = make_float4(0.f, 0.f, 0.f, 0.f);
    float sa = 0.f;

#pragma unroll 1
    for (int t0 = 0; t0 < STEPS; t0 += 4) {
        issueB(t0 + 12);
#pragma unroll
        for (int d = 0; d < 4; d++) {
            const int t = t0 + d;
            const float* sn = ring + ((t + 1) & 15) * 336;
            float4 nd = ((const float4*)(sn))[cg];
            float4 nk = ((const float4*)(sn + 64))[cg];
            float4 nq = ((const float4*)(sn + 128))[cg];
            float4 nr = ((const float4*)(sn + 192))[cg];
            float4 na = ((const float4*)(sn + 256))[cg];
            float  nvi = sn[320 + il];

            s4.x = fmaf(cvi, ck.x, fmaf(sa, cq.x * ca.x, s4.x * cd.x));
            s4.y = fmaf(cvi, ck.y, fmaf(sa, cq.y * ca.y, s4.y * cd.y));
            s4.z = fmaf(cvi, ck.z, fmaf(sa, cq.z * ca.z, s4.z * cd.z));
            s4.w = fmaf(cvi, ck.w, fmaf(sa, cq.w * ca.w, s4.w * cd.w));

            float o  = s4.x * cr.x + s4.y * cr.y + s4.z * cr.z + s4.w * cr.w;
            float sv = s4.x * nq.x + s4.y * nq.y + s4.z * nq.z + s4.w * nq.w;
            o  += __shfl_xor_sync(0xffffffffu, o, 1);
            sv += __shfl_xor_sync(0xffffffffu, sv, 1);
            o  += __shfl_xor_sync(0xffffffffu, o, 2);
            sv += __shfl_xor_sync(0xffffffffu, sv, 2);
            o  += __shfl_xor_sync(0xffffffffu, o, 4);
            sv += __shfl_xor_sync(0xffffffffu, sv, 4);
            o  += __shfl_xor_sync(0xffffffffu, o, 8);
            sv += __shfl_xor_sync(0xffffffffu, sv, 8);
            if (cg == 0) Y[(size_t)t * CC + rowidx] = o;

            sa = -sv;
            cd = nd; ck = nk; cq = nq; cr = nr; ca = na; cvi = nvi;
        }
        asm volatile("cp.async.wait_group 1;" ::: "memory");
        __syncthreads();
    }
}

// ---------------- groupnorm + bonus + gate -> bf16 hi/lo ----------------
__global__ __launch_bounds__(512) void k_gn(
    const float* __restrict__ Yin, const float* __restrict__ R,
    const float* __restrict__ K,   const float* __restrict__ V,
    const float* __restrict__ G,   const float* __restrict__ faaaa,
    const float* __restrict__ lnw, const float* __restrict__ lnb,
    __nv_bfloat16* __restrict__ ymhi, __nv_bfloat16* __restrict__ ymlo) {
    const int t = blockIdx.x, tid = threadIdx.x;
    const int c = tid * 4;
    const size_t idx = (size_t)t * CC + c;
    float4 y  = *(const float4*)&Yin[idx];
    float4 r4 = *(const float4*)&R[idx];
    float4 k4 = *(const float4*)&K[idx];
    float4 v4 = *(const float4*)&V[idx];
    float4 g4 = *(const float4*)&G[idx];
    float4 f4 = *(const float4*)&faaaa[c];
    float4 w4 = *(const float4*)&lnw[c];
    float4 b4 = *(const float4*)&lnb[c];

    float s1 = y.x + y.y + y.z + y.w;
    float s2 = y.x*y.x + y.y*y.y + y.z*y.z + y.w*y.w;
    float s3 = r4.x*k4.x*f4.x + r4.y*k4.y*f4.y + r4.z*k4.z*f4.z + r4.w*k4.w*f4.w;
#pragma unroll
    for (int m = 1; m <= 8; m <<= 1) {
        s1 += __shfl_xor_sync(0xffffffffu, s1, m);
        s2 += __shfl_xor_sync(0xffffffffu, s2, m);
        s3 += __shfl_xor_sync(0xffffffffu, s3, m);
    }
    float mu  = s1 * (1.f / 64.f);
    float var = s2 * (1.f / 64.f) - mu * mu;
    float rs  = rsqrtf(var + EPSGN);
    float o[4];
    o[0] = (fmaf((y.x - mu) * rs, w4.x, b4.x) + s3 * v4.x) * g4.x;
    o[1] = (fmaf((y.y - mu) * rs, w4.y, b4.y) + s3 * v4.y) * g4.y;
    o[2] = (fmaf((y.z - mu) * rs, w4.z, b4.z) + s3 * v4.z) * g4.z;
    o[3] = (fmaf((y.w - mu) * rs, w4.w, b4.w) + s3 * v4.w) * g4.w;
    __nv_bfloat16 hh[4], ll[4];
#pragma unroll
    for (int q = 0; q < 4; q++) {
        hh[q] = __float2bfloat16(o[q]);
        ll[q] = __float2bfloat16(o[q] - __bfloat162float(hh[q]));
    }
    *(uint2*)&ymhi[idx] = *(uint2*)hh;
    *(uint2*)&ymlo[idx] = *(uint2*)ll;
}

// ---------------------------------------------------------------------------
extern "C" void kernel_launch(void* const* d_in, const int* in_sizes, int n_in,
                              void* d_out, int out_size) {
    const float* x      = (const float*)d_in[0];
    const float* Wq     = (const float*)d_in[1];
    const float* Wk     = (const float*)d_in[2];
    const float* Wv     = (const float*)d_in[3];
    const float* Wo     = (const float*)d_in[4];
    const float* tmx    = (const float*)d_in[5];
    const float* tmrg   = (const float*)d_in[6];
    const float* tmwa   = (const float*)d_in[7];
    const float* tmk    = (const float*)d_in[8];
    const float* tmv    = (const float*)d_in[9];
    const float* maa_w1 = (const float*)d_in[10];
    const float* maa_w2 = (const float*)d_in[11];
    const float* tdecay = (const float*)d_in[12];
    const float* dw1    = (const float*)d_in[13];
    const float* dw2    = (const float*)d_in[14];
    const float* taaaaa = (const float*)d_in[15];
    const float* aaa_w1 = (const float*)d_in[16];
    const float* aaa_w2 = (const float*)d_in[17];
    const float* kkk_w1 = (const float*)d_in[18];
    const float* kkk_w2 = (const float*)d_in[19];
    const float* gate_w1 = (const float*)d_in[20];
    const float* gate_w2 = (const float*)d_in[21];
    const float* tmisca = (const float*)d_in[22];
    const float* ma_w1  = (const float*)d_in[23];
    const float* ma_w2  = (const float*)d_in[24];
    const float* tmisck = (const float*)d_in[25];
    const float* mk_w1  = (const float*)d_in[26];
    const float* mk_w2  = (const float*)d_in[27];
    const float* faaaa  = (const float*)d_in[28];
    const float* lnw    = (const float*)d_in[29];
    const float* lnb    = (const float*)d_in[30];
    float* out = (float*)d_out;

    float* S = nullptr;
    cudaGetSymbolAddress((void**)&S, g_scratch);
    __nv_bfloat16* BF = nullptr;
    cudaGetSymbolAddress((void**)&BF, g_bf);

    float* dxp  = S + O_DXP;  float* xxx  = S + O_XXX;
    float* xrg  = S + O_XRG;  float* xwa  = S + O_XWA;
    float* xk   = S + O_XK;   float* xv   = S + O_XV;
    float* R    = S + O_R;    float* Kraw = S + O_KRAW;
    float* V    = S + O_V;    float* Dec  = S + O_DEC;
    float* A    = S + O_A;    float* KK   = S + O_KK;
    float* K    = S + O_K;    float* G    = S + O_G;
    float* Y    = S + O_Y;
    float* hmix = S + O_HMIX; float* gh   = S + O_GH;
    float* hd   = S + O_HD;   float* haaa = S + O_HAAA;
    float* hma  = S + O_HMA;  float* hmk  = S + O_HMK;
    float* hkkk = S + O_HKKK;

    __nv_bfloat16* Wbuf[4][2];
    for (int i = 0; i < 4; i++) {
        Wbuf[i][0] = BF + (size_t)i * 2 * CC * CC;
        Wbuf[i][1] = Wbuf[i][0] + (size_t)CC * CC;
    }
    __nv_bfloat16* Abase = BF + 8ull * CC * CC;
    __nv_bfloat16* ArgH = Abase + 0ull * TC; __nv_bfloat16* ArgL = Abase + 1ull * TC;
    __nv_bfloat16* AkH  = Abase + 2ull * TC; __nv_bfloat16* AkL  = Abase + 3ull * TC;
    __nv_bfloat16* AvH  = Abase + 4ull * TC; __nv_bfloat16* AvL  = Abase + 5ull * TC;
    __nv_bfloat16* AyH  = Abase + 6ull * TC; __nv_bfloat16* AyL  = Abase + 7ull * TC;

    cudaFuncSetAttribute(k_bigmm, cudaFuncAttributeMaxDynamicSharedMemorySize, GM_SMEM);
    cudaFuncSetAttribute(k_stage2, cudaFuncAttributeMaxDynamicSharedMemorySize, S2_SMEM);
    const int PS128 = 2 * (64 * 128 + 512) * 4;
    const int PS64  = 2 * (64 * 64  + 512) * 4;
    const int PS32  = 2 * (64 * 32  + 512) * 4;
    cudaFuncSetAttribute((const void*)k_proj<128,128,1,0>, cudaFuncAttributeMaxDynamicSharedMemorySize, PS128);
    cudaFuncSetAttribute((const void*)k_proj<64,64,1,0>,   cudaFuncAttributeMaxDynamicSharedMemorySize, PS64);
    cudaFuncSetAttribute((const void*)k_proj<32,16,0,0>,   cudaFuncAttributeMaxDynamicSharedMemorySize, PS32);
    cudaFuncSetAttribute((const void*)k_proj<32,16,0,1>,   cudaFuncAttributeMaxDynamicSharedMemorySize, PS32);

    dim3 mg(CC / 128, TT / 128);

    // 1: tokshift + all weight preps
    k_init<<<8192 + 16384, 256>>>(x, tmx, dxp, xxx, Wq, Wk, Wv, Wo, BF);
    // 2
    k_proj<128,128,1,0><<<TT / 8, 256, PS128>>>(xxx, maa_w1, maa_w1, hmix, hmix);
    // 3
    k_mix_apply<<<dim3(CC / 128, TT / 8, 4), 128>>>(x, dxp, hmix, maa_w2,
                                                    tmrg, tmwa, tmk, tmv,
                                                    xrg, xwa, xk, xv,
                                                    ArgH, ArgL, AkH, AkL, AvH, AvL);
    // 4 (ncu capture slot), 5, 6: QKV GEMMs
    k_bigmm<<<mg, 256, GM_SMEM>>>(ArgH, ArgL, Wbuf[0][0], Wbuf[0][1], R);
    k_bigmm<<<mg, 256, GM_SMEM>>>(AkH, AkL, Wbuf[1][0], Wbuf[1][1], Kraw);
    k_bigmm<<<mg, 256, GM_SMEM>>>(AvH, AvL, Wbuf[2][0], Wbuf[2][1], V);

    k_proj<128,128,1,0><<<TT / 8, 256, PS128>>>(xrg, gate_w1, gate_w1, gh, gh);
    k_proj<64,64,1,0>  <<<TT / 8, 256, PS64 >>>(xwa, dw1, dw1, hd, hd);
    k_proj<32,16,0,0>  <<<TT / 8, 256, PS32 >>>(xwa, aaa_w1, ma_w1, haaa, hma);
    k_proj<32,16,0,1>  <<<TT / 8, 256, PS32 >>>(xk,  mk_w1, kkk_w1, hmk, hkkk);

    k_stage2<<<TT / 8, 256, S2_SMEM>>>(Kraw, hd, haaa, hma, hmk, hkkk, gh,
                                       tdecay, dw2, taaaaa, aaa_w2, tmisca, ma_w2,
                                       tmisck, mk_w2, kkk_w2, gate_w2,
                                       Dec, A, KK, K, G);
    k_wkv<TT><<<dim3(HH, 4), 256>>>(R, Dec, K, KK, A, V, Y);
    k_gn<<<TT, 512>>>(Y, R, K, V, G, faaaa, lnw, lnb, AyH, AyL);
    k_bigmm<<<mg, 256, GM_SMEM>>>(AyH, AyL, Wbuf[3][0], Wbuf[3][1], out);
}